// round 8
// baseline (speedup 1.0000x reference)
#include <cuda_runtime.h>

#define NPTS 2048
// smem: sG 6144 (aliased by sH 4608 in phase 7+) | sA2 12288 | smalls 3584 = 22016 fl
#define SMEM_FLOATS 22016
#define SMEM_BYTES (SMEM_FLOATS * 4)

// -------- scratch (device globals: allocation-free) --------
__device__ float d_We21[128 * 64];
__device__ float d_WkT[65 * 128];     // +1 pad row for prefetch overrun
__device__ float d_WvT[65 * 128];     // +1 pad row
__device__ float d_WqT[64 * 128];
__device__ float d_Wr[128];
__device__ float d_Wf1T[392 * 128];   // +8 pad rows
__device__ float d_Wf2T[136 * 128];   // +8 pad rows
__device__ float d_bf2s[128];
__device__ float d_q[NPTS * 384];
__device__ float d_Ax[NPTS * 128 * 32];          // logits   [p][o][s]
__device__ float d_Vpr[NPTS * 128 * 3 * 32];     // v + pos  [p][o][d][s]

// -------- packed f32x2 helpers (SASS FFMA2 path, PTX-only) --------
__device__ __forceinline__ void ffma2(unsigned long long& d,
                                      unsigned long long a,
                                      unsigned long long b) {
    asm("fma.rn.f32x2 %0, %1, %2, %0;" : "+l"(d) : "l"(a), "l"(b));
}
__device__ __forceinline__ unsigned long long pack2(float x) {
    unsigned long long r;
    asm("mov.b64 %0, {%1, %1};" : "=l"(r) : "f"(x));
    return r;
}
__device__ __forceinline__ float2 unpack2(unsigned long long v) {
    float2 f;
    asm("mov.b64 {%0, %1}, %2;" : "=f"(f.x), "=f"(f.y) : "l"(v));
    return f;
}

// ---------------- prep1: We21 = We2 @ We1  (128x64) ----------------
__global__ void prep1_kernel(const float* __restrict__ We1, const float* __restrict__ We2) {
    int t = blockIdx.x, c = threadIdx.x;
    float a = 0.f;
#pragma unroll 8
    for (int e = 0; e < 128; e++) a += We2[t * 128 + e] * We1[e * 64 + c];
    d_We21[t * 64 + c] = a;
}

// ---------------- prep2: fold q/k/v + transpose f1/f2 + Wr ----------------
__global__ void prep2_kernel(const float* __restrict__ Wq, const float* __restrict__ Wk,
                             const float* __restrict__ Wv, const float* __restrict__ Wr1,
                             const float* __restrict__ Wr2, const float* __restrict__ Wf1,
                             const float* __restrict__ Wf2, const float* __restrict__ bf2) {
    const float invS = 0.08838834764831845f;  // 1/sqrt(128)
    int o = blockIdx.x, c = threadIdx.x;
    float ak = 0.f, av = 0.f, aq = 0.f;
#pragma unroll 8
    for (int x = 0; x < 128; x++) {
        float w21 = d_We21[x * 64 + c];
        ak += Wk[o * 128 + x] * w21;
        av += Wv[o * 128 + x] * w21;
        aq += Wq[o * 128 + x] * w21;
    }
    d_WkT[c * 128 + o] = ak;
    d_WvT[c * 128 + o] = av;
    d_WqT[c * 128 + o] = aq;
#pragma unroll
    for (int u = 0; u < 6; u++) { int cc = u * 64 + c; d_Wf1T[cc * 128 + o] = Wf1[o * 384 + cc]; }
#pragma unroll
    for (int u = 0; u < 2; u++) { int cc = u * 64 + c; d_Wf2T[cc * 128 + o] = Wf2[o * 128 + cc] * invS; }
    __shared__ float red[64];
    red[c] = Wr2[o * 64 + c] * Wr1[c];
    __syncthreads();
    if (c == 0) {
        float r = 0.f;
#pragma unroll
        for (int i = 0; i < 64; i++) r += red[i];
        d_Wr[o] = r;
        d_bf2s[o] = bf2[o] * invS;
    }
    // zero prefetch-overrun pad rows
    if (o == 0) {
        d_WkT[64 * 128 + c * 2] = 0.f; d_WkT[64 * 128 + c * 2 + 1] = 0.f;
        d_WvT[64 * 128 + c * 2] = 0.f; d_WvT[64 * 128 + c * 2 + 1] = 0.f;
#pragma unroll
        for (int u = 0; u < 8; u++) { d_Wf1T[(384 + u) * 128 + c * 2] = 0.f; d_Wf1T[(384 + u) * 128 + c * 2 + 1] = 0.f; }
#pragma unroll
        for (int u = 0; u < 8; u++) { d_Wf2T[(128 + u) * 128 + c * 2] = 0.f; d_Wf2T[(128 + u) * 128 + c * 2 + 1] = 0.f; }
    }
}

// ---------------- per-point q (from s=0 column of group_fts) ----------------
__global__ void q_kernel(const float* __restrict__ gfts) {
    int p = blockIdx.x;             // b*1024 + n
    int b = p >> 10, n = p & 1023;
    int o = threadIdx.x;            // 128 threads
    const float* gbase = gfts + (size_t)b * 6291456u + (size_t)n * 32u;
    float acc0 = 0.f, acc1 = 0.f, acc2 = 0.f;
#pragma unroll 4
    for (int c = 0; c < 64; c++) {
        float w = d_WqT[c * 128 + o];
        acc0 += w * gbase[c * 98304 + 0 * 32768];
        acc1 += w * gbase[c * 98304 + 1 * 32768];
        acc2 += w * gbase[c * 98304 + 2 * 32768];
    }
    d_q[p * 384 + o * 3 + 0] = acc0;
    d_q[p * 384 + o * 3 + 1] = acc1;
    d_q[p * 384 + o * 3 + 2] = acc2;
}

// ---------------- warp reductions ----------------
__device__ __forceinline__ float wmax(float v) {
#pragma unroll
    for (int m = 16; m; m >>= 1) v = fmaxf(v, __shfl_xor_sync(0xffffffffu, v, m));
    return v;
}
__device__ __forceinline__ float wsum(float v) {
#pragma unroll
    for (int m = 16; m; m >>= 1) v += __shfl_xor_sync(0xffffffffu, v, m);
    return v;
}

// ---------------- main kernel: one CTA per point, 2 CTAs/SM ----------------
__global__ __launch_bounds__(256, 2)
void main_kernel(const float* __restrict__ gxyz, const float* __restrict__ gfts,
                 const float* __restrict__ qxyz, const float* __restrict__ Wstd,
                 const float* __restrict__ bf1) {
    extern __shared__ float smf[];
    float* sG    = smf;             // [64][3][32]  (6144) — dead after v-pass
    float* sH    = smf;             // [128][36]    (4608) aliases sG, phase 7+
    float* sA2   = smf + 6144;      // [384][32]    (12288)
    float* sXr   = smf + 18432;     // [3][32]
    float* sQ    = smf + 18528;     // [384]
    float* sWr   = smf + 18912;     // [128]
    float* sWstd = smf + 19040;     // [3][128]
    float* sZp   = smf + 19424;     // [8][32][9]
    float* sZ    = smf + 21728;     // [9][32]

    const int p = blockIdx.x;
    const int b = p >> 10, n = p & 1023;
    const int tid = threadIdx.x;

    // ---- cooperative loads ----
    {
        const float4* gb4 = (const float4*)(gfts + (size_t)b * 6291456u + (size_t)n * 32u);
        for (int idx = tid; idx < 1536; idx += 256) {
            int c = idx / 24;
            int rem = idx - c * 24;
            int d = rem >> 3, s4 = rem & 7;
            ((float4*)sG)[idx] = gb4[c * 24576 + d * 8192 + s4];
        }
        for (int idx = tid; idx < 384; idx += 256) {
            sQ[idx] = d_q[p * 384 + idx];
            sWstd[idx] = Wstd[idx];
        }
        if (tid < 128) sWr[tid] = d_Wr[tid];
        if (tid < 96) {
            int d = tid >> 5, s = tid & 31;
            sXr[tid] = gxyz[((size_t)p * 32 + s) * 3 + d] - qxyz[(size_t)p * 3 + d];
        }
    }
    __syncthreads();

    const int s = tid & 31, r = tid >> 5, o0 = r << 4;
    const float xr0 = sXr[s], xr1 = sXr[32 + s], xr2 = sXr[64 + s];

    // ---- k-pass: k = WkT^T @ g via FFMA2, weights streamed via broadcast LDG ----
    float at[16][3];
    {
        unsigned long long atp[8][3];
#pragma unroll
        for (int jp = 0; jp < 8; jp++)
#pragma unroll
            for (int d = 0; d < 3; d++) atp[jp][d] = 0ull;

        const ulonglong2* wkp = (const ulonglong2*)(d_WkT + o0);  // row stride 32 ull2
        ulonglong2 w0 = __ldg(wkp + 0), w1 = __ldg(wkp + 1),
                   w2 = __ldg(wkp + 2), w3 = __ldg(wkp + 3);
#pragma unroll 2
        for (int c = 0; c < 64; c++) {
            const ulonglong2* nx = wkp + (c + 1) * 32;
            ulonglong2 n0 = __ldg(nx + 0), n1 = __ldg(nx + 1),
                       n2 = __ldg(nx + 2), n3 = __ldg(nx + 3);
            unsigned long long g0p = pack2(sG[c * 96 + s]);
            unsigned long long g1p = pack2(sG[c * 96 + 32 + s]);
            unsigned long long g2p = pack2(sG[c * 96 + 64 + s]);
            ffma2(atp[0][0], w0.x, g0p); ffma2(atp[0][1], w0.x, g1p); ffma2(atp[0][2], w0.x, g2p);
            ffma2(atp[1][0], w0.y, g0p); ffma2(atp[1][1], w0.y, g1p); ffma2(atp[1][2], w0.y, g2p);
            ffma2(atp[2][0], w1.x, g0p); ffma2(atp[2][1], w1.x, g1p); ffma2(atp[2][2], w1.x, g2p);
            ffma2(atp[3][0], w1.y, g0p); ffma2(atp[3][1], w1.y, g1p); ffma2(atp[3][2], w1.y, g2p);
            ffma2(atp[4][0], w2.x, g0p); ffma2(atp[4][1], w2.x, g1p); ffma2(atp[4][2], w2.x, g2p);
            ffma2(atp[5][0], w2.y, g0p); ffma2(atp[5][1], w2.y, g1p); ffma2(atp[5][2], w2.y, g2p);
            ffma2(atp[6][0], w3.x, g0p); ffma2(atp[6][1], w3.x, g1p); ffma2(atp[6][2], w3.x, g2p);
            ffma2(atp[7][0], w3.y, g0p); ffma2(atp[7][1], w3.y, g1p); ffma2(atp[7][2], w3.y, g2p);
            w0 = n0; w1 = n1; w2 = n2; w3 = n3;
        }
        // attn = q - k + pr
#pragma unroll
        for (int jp = 0; jp < 8; jp++) {
            int ia = jp * 2, ib = jp * 2 + 1;
            float wra = sWr[o0 + ia], wrb = sWr[o0 + ib];
            float2 k0 = unpack2(atp[jp][0]);
            float2 k1 = unpack2(atp[jp][1]);
            float2 k2 = unpack2(atp[jp][2]);
            at[ia][0] = sQ[(o0 + ia) * 3 + 0] - k0.x + wra * xr0;
            at[ib][0] = sQ[(o0 + ib) * 3 + 0] - k0.y + wrb * xr0;
            at[ia][1] = sQ[(o0 + ia) * 3 + 1] - k1.x + wra * xr1;
            at[ib][1] = sQ[(o0 + ib) * 3 + 1] - k1.y + wrb * xr1;
            at[ia][2] = sQ[(o0 + ia) * 3 + 2] - k2.x + wra * xr2;
            at[ib][2] = sQ[(o0 + ib) * 3 + 2] - k2.y + wrb * xr2;
        }
    }

    // ---- z0 partials ----
    {
        float pz[9];
#pragma unroll
        for (int jk = 0; jk < 9; jk++) pz[jk] = 0.f;
#pragma unroll
        for (int i = 0; i < 16; i++) {
            float w0 = sWstd[o0 + i];
            float w1 = sWstd[128 + o0 + i];
            float w2 = sWstd[256 + o0 + i];
#pragma unroll
            for (int k = 0; k < 3; k++) {
                float a = at[i][k];
                pz[0 * 3 + k] += w0 * a;
                pz[1 * 3 + k] += w1 * a;
                pz[2 * 3 + k] += w2 * a;
            }
        }
#pragma unroll
        for (int jk = 0; jk < 9; jk++) sZp[(r * 32 + s) * 9 + jk] = pz[jk];
    }
    __syncthreads();
    if (r == 0) {
#pragma unroll
        for (int jk = 0; jk < 9; jk++) {
            float v = 0.f;
#pragma unroll
            for (int rr = 0; rr < 8; rr++) v += sZp[(rr * 32 + s) * 9 + jk];
            sZ[jk * 32 + s] = v;
        }
    }
    __syncthreads();

    // ---- attn2 = attn @ z0 -> sA2 [384][32]  (frees at) ----
    {
        float z[9];
#pragma unroll
        for (int jk = 0; jk < 9; jk++) z[jk] = sZ[jk * 32 + s];
#pragma unroll
        for (int i = 0; i < 16; i++) {
#pragma unroll
            for (int k = 0; k < 3; k++) {
                float a2 = at[i][0] * z[0 * 3 + k] + at[i][1] * z[1 * 3 + k] + at[i][2] * z[2 * 3 + k];
                sA2[((o0 + i) * 3 + k) * 32 + s] = a2;
            }
        }
    }

    // ---- v-pass: v = WvT^T @ g ; vpr = v + pr -> GLOBAL ----
    {
        unsigned long long vpp[8][3];
#pragma unroll
        for (int jp = 0; jp < 8; jp++)
#pragma unroll
            for (int d = 0; d < 3; d++) vpp[jp][d] = 0ull;

        const ulonglong2* wvp = (const ulonglong2*)(d_WvT + o0);
        ulonglong2 w0 = __ldg(wvp + 0), w1 = __ldg(wvp + 1),
                   w2 = __ldg(wvp + 2), w3 = __ldg(wvp + 3);
#pragma unroll 2
        for (int c = 0; c < 64; c++) {
            const ulonglong2* nx = wvp + (c + 1) * 32;
            ulonglong2 n0 = __ldg(nx + 0), n1 = __ldg(nx + 1),
                       n2 = __ldg(nx + 2), n3 = __ldg(nx + 3);
            unsigned long long g0p = pack2(sG[c * 96 + s]);
            unsigned long long g1p = pack2(sG[c * 96 + 32 + s]);
            unsigned long long g2p = pack2(sG[c * 96 + 64 + s]);
            ffma2(vpp[0][0], w0.x, g0p); ffma2(vpp[0][1], w0.x, g1p); ffma2(vpp[0][2], w0.x, g2p);
            ffma2(vpp[1][0], w0.y, g0p); ffma2(vpp[1][1], w0.y, g1p); ffma2(vpp[1][2], w0.y, g2p);
            ffma2(vpp[2][0], w1.x, g0p); ffma2(vpp[2][1], w1.x, g1p); ffma2(vpp[2][2], w1.x, g2p);
            ffma2(vpp[3][0], w1.y, g0p); ffma2(vpp[3][1], w1.y, g1p); ffma2(vpp[3][2], w1.y, g2p);
            ffma2(vpp[4][0], w2.x, g0p); ffma2(vpp[4][1], w2.x, g1p); ffma2(vpp[4][2], w2.x, g2p);
            ffma2(vpp[5][0], w2.y, g0p); ffma2(vpp[5][1], w2.y, g1p); ffma2(vpp[5][2], w2.y, g2p);
            ffma2(vpp[6][0], w3.x, g0p); ffma2(vpp[6][1], w3.x, g1p); ffma2(vpp[6][2], w3.x, g2p);
            ffma2(vpp[7][0], w3.y, g0p); ffma2(vpp[7][1], w3.y, g1p); ffma2(vpp[7][2], w3.y, g2p);
            w0 = n0; w1 = n1; w2 = n2; w3 = n3;
        }
        float* vout = d_Vpr + (size_t)(p * 128 + o0) * 96 + s;
#pragma unroll
        for (int jp = 0; jp < 8; jp++) {
            int ia = jp * 2, ib = jp * 2 + 1;
            float wra = sWr[o0 + ia], wrb = sWr[o0 + ib];
            float2 v0 = unpack2(vpp[jp][0]);
            float2 v1 = unpack2(vpp[jp][1]);
            float2 v2 = unpack2(vpp[jp][2]);
            vout[ia * 96 + 0]  = v0.x + wra * xr0;
            vout[ib * 96 + 0]  = v0.y + wrb * xr0;
            vout[ia * 96 + 32] = v1.x + wra * xr1;
            vout[ib * 96 + 32] = v1.y + wrb * xr1;
            vout[ia * 96 + 64] = v2.x + wra * xr2;
            vout[ib * 96 + 64] = v2.y + wrb * xr2;
        }
    }
    __syncthreads();   // sA2 complete (all warps), sG dead -> sH alias safe

    // ---- f1 GEMM 128x384 over s=32; weights streamed from L2 w/ prefetch ----
    const int oo = tid & 127, sg = tid >> 7;
    unsigned long long hp[8];
#pragma unroll
    for (int q = 0; q < 8; q++) hp[q] = 0ull;
    {
        float wc[4], wn[4];
#pragma unroll
        for (int j = 0; j < 4; j++) wc[j] = d_Wf1T[j * 128 + oo];
        for (int cb = 0; cb < 384; cb += 4) {
#pragma unroll
            for (int j = 0; j < 4; j++) wn[j] = d_Wf1T[(cb + 4 + j) * 128 + oo];
#pragma unroll
            for (int j = 0; j < 4; j++) {
                unsigned long long wp = pack2(wc[j]);
                const ulonglong2* av2 = (const ulonglong2*)(sA2 + (cb + j) * 32 + sg * 16);
#pragma unroll
                for (int qq = 0; qq < 4; qq++) {
                    ulonglong2 a = av2[qq];
                    ffma2(hp[qq * 2 + 0], a.x, wp);
                    ffma2(hp[qq * 2 + 1], a.y, wp);
                }
            }
#pragma unroll
            for (int j = 0; j < 4; j++) wc[j] = wn[j];
        }
    }
    {
        float bb = bf1[oo];
#pragma unroll
        for (int q2 = 0; q2 < 8; q2++) {
            float2 h = unpack2(hp[q2]);
            sH[oo * 36 + sg * 16 + q2 * 2 + 0] = fmaxf(h.x + bb, 0.f);
            sH[oo * 36 + sg * 16 + q2 * 2 + 1] = fmaxf(h.y + bb, 0.f);
        }
    }
    __syncthreads();

    // ---- f2 GEMM 128x128; logits -> GLOBAL ----
    unsigned long long ap[8];
#pragma unroll
    for (int q = 0; q < 8; q++) ap[q] = 0ull;
    {
        float wc[4], wn[4];
#pragma unroll
        for (int j = 0; j < 4; j++) wc[j] = d_Wf2T[j * 128 + oo];
        for (int cb = 0; cb < 128; cb += 4) {
#pragma unroll
            for (int j = 0; j < 4; j++) wn[j] = d_Wf2T[(cb + 4 + j) * 128 + oo];
#pragma unroll
            for (int j = 0; j < 4; j++) {
                unsigned long long wp = pack2(wc[j]);
                const ulonglong2* hv2 = (const ulonglong2*)(sH + (cb + j) * 36 + sg * 16);
#pragma unroll
                for (int qq = 0; qq < 4; qq++) {
                    ulonglong2 h = hv2[qq];
                    ffma2(ap[qq * 2 + 0], h.x, wp);
                    ffma2(ap[qq * 2 + 1], h.y, wp);
                }
            }
#pragma unroll
            for (int j = 0; j < 4; j++) wc[j] = wn[j];
        }
    }
    {
        float bb = d_bf2s[oo];   // 1/sqrt(128) folded into Wf2T and bf2s
        float4* axo = (float4*)(d_Ax + (size_t)(p * 128 + oo) * 32 + sg * 16);
#pragma unroll
        for (int q4 = 0; q4 < 4; q4++) {
            float2 a0 = unpack2(ap[q4 * 2 + 0]);
            float2 a1 = unpack2(ap[q4 * 2 + 1]);
            axo[q4] = make_float4(a0.x + bb, a0.y + bb, a1.x + bb, a1.y + bb);
        }
    }
}

// ---------------- finish: softmax over s + weighted sum over s ----------------
__global__ __launch_bounds__(256)
void finish_kernel(float* __restrict__ out) {
    const int p = blockIdx.x;
    const int b = p >> 10, n = p & 1023;
    const int tid = threadIdx.x;
    const int s = tid & 31, r = tid >> 5, o0 = r << 4;
    const float* ax = d_Ax + (size_t)(p * 128) * 32 + s;
    const float* vr = d_Vpr + (size_t)(p * 128) * 96 + s;
#pragma unroll 2
    for (int i = 0; i < 16; i++) {
        int o = o0 + i;
        float x = ax[o * 32];
        float v0 = vr[o * 96];
        float v1 = vr[o * 96 + 32];
        float v2 = vr[o * 96 + 64];
        float m = wmax(x);
        float e = __expf(x - m);
        float denom = wsum(e);
        float w = e / denom;
        float r0 = wsum(w * v0);
        float r1 = wsum(w * v1);
        float r2 = wsum(w * v2);
        if (s == 0) {
            size_t base = (((size_t)b * 128 + o) * 3) * 1024 + n;
            out[base] = r0;
            out[base + 1024] = r1;
            out[base + 2048] = r2;
        }
    }
}

extern "C" void kernel_launch(void* const* d_in, const int* in_sizes, int n_in,
                              void* d_out, int out_size) {
    (void)in_sizes; (void)n_in; (void)out_size;
    const float* gxyz = (const float*)d_in[0];
    const float* gfts = (const float*)d_in[1];
    const float* qxyz = (const float*)d_in[2];
    cudaFuncSetAttribute(main_kernel, cudaFuncAttributeMaxDynamicSharedMemorySize, SMEM_BYTES);
    prep1_kernel<<<128, 64>>>((const float*)d_in[3], (const float*)d_in[4]);
    prep2_kernel<<<128, 64>>>((const float*)d_in[5],  (const float*)d_in[6],
                              (const float*)d_in[7],  (const float*)d_in[8],
                              (const float*)d_in[9],  (const float*)d_in[11],
                              (const float*)d_in[13], (const float*)d_in[14]);
    q_kernel<<<NPTS, 128>>>(gfts);
    main_kernel<<<NPTS, 256, SMEM_BYTES>>>(gxyz, gfts, qxyz,
                                           (const float*)d_in[10],
                                           (const float*)d_in[12]);
    finish_kernel<<<NPTS, 256>>>((float*)d_out);
}

// round 10
// speedup vs baseline: 1.2092x; 1.2092x over previous
#include <cuda_runtime.h>

#define NPTS 2048
// smem map (floats):
//   [0,6144)      sG   [64][3][32]        (aliased by sH [128][36]=4608 after v-pass)
//   [6144,14336)  sWb  [64][128] staged Wk then Wv  (aliased by sAx [128][34]=4352 after v-pass)
//   [14336,26624) sA2  [384][32]          (first 2304 alias sZp [8][32][9] before A2 written)
//   [26624,27904) smalls: sXr 96 | sQ 384 | sWr 128 | sWstd 384 | sZ 288
#define SMEM_FLOATS 27904
#define SMEM_BYTES (SMEM_FLOATS * 4)

// -------- scratch (device globals: allocation-free) --------
__device__ float d_We21[128 * 64];
__device__ float d_WkT[64 * 128];
__device__ float d_WvT[64 * 128];
__device__ float d_WqT[64 * 128];
__device__ float d_Wr[128];
__device__ float d_Wf1T[392 * 128];   // +8 pad rows for prefetch overrun
__device__ float d_Wf2T[136 * 128];   // +8 pad rows
__device__ float d_bf2s[128];
__device__ float d_q[NPTS * 384];

// -------- packed f32x2 helpers (SASS FFMA2 path, PTX-only) --------
__device__ __forceinline__ void ffma2(unsigned long long& d,
                                      unsigned long long a,
                                      unsigned long long b) {
    asm("fma.rn.f32x2 %0, %1, %2, %0;" : "+l"(d) : "l"(a), "l"(b));
}
__device__ __forceinline__ unsigned long long pack2(float x) {
    unsigned long long r;
    asm("mov.b64 %0, {%1, %1};" : "=l"(r) : "f"(x));
    return r;
}
__device__ __forceinline__ float2 unpack2(unsigned long long v) {
    float2 f;
    asm("mov.b64 {%0, %1}, %2;" : "=f"(f.x), "=f"(f.y) : "l"(v));
    return f;
}

// ---------------- prep1: We21 = We2 @ We1  (128x64) ----------------
__global__ void prep1_kernel(const float* __restrict__ We1, const float* __restrict__ We2) {
    int t = blockIdx.x, c = threadIdx.x;
    float a = 0.f;
#pragma unroll 8
    for (int e = 0; e < 128; e++) a += We2[t * 128 + e] * We1[e * 64 + c];
    d_We21[t * 64 + c] = a;
}

// ---------------- prep2: fold q/k/v + transpose f1/f2 + Wr ----------------
__global__ void prep2_kernel(const float* __restrict__ Wq, const float* __restrict__ Wk,
                             const float* __restrict__ Wv, const float* __restrict__ Wr1,
                             const float* __restrict__ Wr2, const float* __restrict__ Wf1,
                             const float* __restrict__ Wf2, const float* __restrict__ bf2) {
    const float invS = 0.08838834764831845f;  // 1/sqrt(128)
    int o = blockIdx.x, c = threadIdx.x;
    float ak = 0.f, av = 0.f, aq = 0.f;
#pragma unroll 8
    for (int x = 0; x < 128; x++) {
        float w21 = d_We21[x * 64 + c];
        ak += Wk[o * 128 + x] * w21;
        av += Wv[o * 128 + x] * w21;
        aq += Wq[o * 128 + x] * w21;
    }
    d_WkT[c * 128 + o] = ak;
    d_WvT[c * 128 + o] = av;
    d_WqT[c * 128 + o] = aq;
#pragma unroll
    for (int u = 0; u < 6; u++) { int cc = u * 64 + c; d_Wf1T[cc * 128 + o] = Wf1[o * 384 + cc]; }
#pragma unroll
    for (int u = 0; u < 2; u++) { int cc = u * 64 + c; d_Wf2T[cc * 128 + o] = Wf2[o * 128 + cc] * invS; }
    __shared__ float red[64];
    red[c] = Wr2[o * 64 + c] * Wr1[c];
    __syncthreads();
    if (c == 0) {
        float r = 0.f;
#pragma unroll
        for (int i = 0; i < 64; i++) r += red[i];
        d_Wr[o] = r;
        d_bf2s[o] = bf2[o] * invS;
    }
    // zero prefetch-overrun pad rows of f1/f2 weights
    if (o == 0) {
#pragma unroll
        for (int u = 0; u < 8; u++) { d_Wf1T[(384 + u) * 128 + c * 2] = 0.f; d_Wf1T[(384 + u) * 128 + c * 2 + 1] = 0.f; }
#pragma unroll
        for (int u = 0; u < 8; u++) { d_Wf2T[(128 + u) * 128 + c * 2] = 0.f; d_Wf2T[(128 + u) * 128 + c * 2 + 1] = 0.f; }
    }
}

// ---------------- per-point q (from s=0 column of group_fts) ----------------
__global__ void q_kernel(const float* __restrict__ gfts) {
    int p = blockIdx.x;             // b*1024 + n
    int b = p >> 10, n = p & 1023;
    int o = threadIdx.x;            // 128 threads
    const float* gbase = gfts + (size_t)b * 6291456u + (size_t)n * 32u;
    float acc0 = 0.f, acc1 = 0.f, acc2 = 0.f;
#pragma unroll 4
    for (int c = 0; c < 64; c++) {
        float w = d_WqT[c * 128 + o];
        acc0 += w * gbase[c * 98304 + 0 * 32768];
        acc1 += w * gbase[c * 98304 + 1 * 32768];
        acc2 += w * gbase[c * 98304 + 2 * 32768];
    }
    d_q[p * 384 + o * 3 + 0] = acc0;
    d_q[p * 384 + o * 3 + 1] = acc1;
    d_q[p * 384 + o * 3 + 2] = acc2;
}

// ---------------- warp reductions ----------------
__device__ __forceinline__ float wmax(float v) {
#pragma unroll
    for (int m = 16; m; m >>= 1) v = fmaxf(v, __shfl_xor_sync(0xffffffffu, v, m));
    return v;
}
__device__ __forceinline__ float wsum(float v) {
#pragma unroll
    for (int m = 16; m; m >>= 1) v += __shfl_xor_sync(0xffffffffu, v, m);
    return v;
}

// ---------------- fully fused main kernel: one CTA per point, 2 CTAs/SM ----------------
__global__ __launch_bounds__(256, 2)
void main_kernel(const float* __restrict__ gxyz, const float* __restrict__ gfts,
                 const float* __restrict__ qxyz, const float* __restrict__ Wstd,
                 const float* __restrict__ bf1, float* __restrict__ out) {
    extern __shared__ float smf[];
    float* sG    = smf;             // [64][3][32]
    float* sWb   = smf + 6144;      // [64][128]  staged Wk, then Wv
    float* sA2   = smf + 14336;     // [384][32]
    float* sZp   = smf + 14336;     // [8][32][9] alias (dead before A2 written)
    float* sH    = smf;             // [128][36]  alias sG (after v-pass)
    float* sAx   = smf + 6144;      // [128][34]  alias sWb (after v-pass); stride 34 -> 8B-aligned rows
    float* sXr   = smf + 26624;     // [3][32]
    float* sQ    = smf + 26720;     // [384]
    float* sWr   = smf + 27104;     // [128]
    float* sWstd = smf + 27232;     // [3][128]
    float* sZ    = smf + 27616;     // [9][32]

    const int p = blockIdx.x;
    const int b = p >> 10, n = p & 1023;
    const int tid = threadIdx.x;

    // ---- cooperative loads: G, Wk, smalls ----
    {
        const float4* gb4 = (const float4*)(gfts + (size_t)b * 6291456u + (size_t)n * 32u);
        for (int idx = tid; idx < 1536; idx += 256) {
            int c = idx / 24;
            int rem = idx - c * 24;
            int d = rem >> 3, s4 = rem & 7;
            ((float4*)sG)[idx] = gb4[c * 24576 + d * 8192 + s4];
        }
        for (int idx = tid; idx < 2048; idx += 256)
            ((float4*)sWb)[idx] = ((const float4*)d_WkT)[idx];
        for (int idx = tid; idx < 384; idx += 256) {
            sQ[idx] = d_q[p * 384 + idx];
            sWstd[idx] = Wstd[idx];
        }
        if (tid < 128) sWr[tid] = d_Wr[tid];
        if (tid < 96) {
            int d = tid >> 5, s = tid & 31;
            sXr[tid] = gxyz[((size_t)p * 32 + s) * 3 + d] - qxyz[(size_t)p * 3 + d];
        }
    }
    __syncthreads();

    const int s = tid & 31, r = tid >> 5, o0 = r << 4;
    const float xr0 = sXr[s], xr1 = sXr[32 + s], xr2 = sXr[64 + s];

    // ---- k-pass: k = WkT^T @ g via FFMA2 (weights from smem, broadcast) ----
    float at[16][3];
    {
        unsigned long long atp[8][3];
#pragma unroll
        for (int jp = 0; jp < 8; jp++)
#pragma unroll
            for (int d = 0; d < 3; d++) atp[jp][d] = 0ull;
#pragma unroll 2
        for (int c = 0; c < 64; c++) {
            unsigned long long g0p = pack2(sG[c * 96 + s]);
            unsigned long long g1p = pack2(sG[c * 96 + 32 + s]);
            unsigned long long g2p = pack2(sG[c * 96 + 64 + s]);
            const ulonglong2* w2 = (const ulonglong2*)(sWb + c * 128 + o0);
            ulonglong2 wa = w2[0], wb = w2[1], wc = w2[2], wd = w2[3];
            ffma2(atp[0][0], wa.x, g0p); ffma2(atp[0][1], wa.x, g1p); ffma2(atp[0][2], wa.x, g2p);
            ffma2(atp[1][0], wa.y, g0p); ffma2(atp[1][1], wa.y, g1p); ffma2(atp[1][2], wa.y, g2p);
            ffma2(atp[2][0], wb.x, g0p); ffma2(atp[2][1], wb.x, g1p); ffma2(atp[2][2], wb.x, g2p);
            ffma2(atp[3][0], wb.y, g0p); ffma2(atp[3][1], wb.y, g1p); ffma2(atp[3][2], wb.y, g2p);
            ffma2(atp[4][0], wc.x, g0p); ffma2(atp[4][1], wc.x, g1p); ffma2(atp[4][2], wc.x, g2p);
            ffma2(atp[5][0], wc.y, g0p); ffma2(atp[5][1], wc.y, g1p); ffma2(atp[5][2], wc.y, g2p);
            ffma2(atp[6][0], wd.x, g0p); ffma2(atp[6][1], wd.x, g1p); ffma2(atp[6][2], wd.x, g2p);
            ffma2(atp[7][0], wd.y, g0p); ffma2(atp[7][1], wd.y, g1p); ffma2(atp[7][2], wd.y, g2p);
        }
        // attn = q - k + pr
#pragma unroll
        for (int jp = 0; jp < 8; jp++) {
            int ia = jp * 2, ib = jp * 2 + 1;
            float wra = sWr[o0 + ia], wrb = sWr[o0 + ib];
            float2 k0 = unpack2(atp[jp][0]);
            float2 k1 = unpack2(atp[jp][1]);
            float2 k2 = unpack2(atp[jp][2]);
            at[ia][0] = sQ[(o0 + ia) * 3 + 0] - k0.x + wra * xr0;
            at[ib][0] = sQ[(o0 + ib) * 3 + 0] - k0.y + wrb * xr0;
            at[ia][1] = sQ[(o0 + ia) * 3 + 1] - k1.x + wra * xr1;
            at[ib][1] = sQ[(o0 + ib) * 3 + 1] - k1.y + wrb * xr1;
            at[ia][2] = sQ[(o0 + ia) * 3 + 2] - k2.x + wra * xr2;
            at[ib][2] = sQ[(o0 + ib) * 3 + 2] - k2.y + wrb * xr2;
        }
    }

    // ---- z0 partials (into sZp, alias of sA2 — A2 not yet written) ----
    {
        float pz[9];
#pragma unroll
        for (int jk = 0; jk < 9; jk++) pz[jk] = 0.f;
#pragma unroll
        for (int i = 0; i < 16; i++) {
            float w0 = sWstd[o0 + i];
            float w1 = sWstd[128 + o0 + i];
            float w2 = sWstd[256 + o0 + i];
#pragma unroll
            for (int k = 0; k < 3; k++) {
                float a = at[i][k];
                pz[0 * 3 + k] += w0 * a;
                pz[1 * 3 + k] += w1 * a;
                pz[2 * 3 + k] += w2 * a;
            }
        }
#pragma unroll
        for (int jk = 0; jk < 9; jk++) sZp[(r * 32 + s) * 9 + jk] = pz[jk];
    }
    __syncthreads();   // k-pass reads of sWb complete; sZp visible

    // ---- overlap: warp 0 reduces z0; everyone restages Wv into sWb ----
    for (int idx = tid; idx < 2048; idx += 256)
        ((float4*)sWb)[idx] = ((const float4*)d_WvT)[idx];
    if (r == 0) {
#pragma unroll
        for (int jk = 0; jk < 9; jk++) {
            float v = 0.f;
#pragma unroll
            for (int rr = 0; rr < 8; rr++) v += sZp[(rr * 32 + s) * 9 + jk];
            sZ[jk * 32 + s] = v;
        }
    }
    __syncthreads();

    // ---- attn2 = attn @ z0 -> sA2 (clobbers sZp, now dead) ----
    {
        float z[9];
#pragma unroll
        for (int jk = 0; jk < 9; jk++) z[jk] = sZ[jk * 32 + s];
#pragma unroll
        for (int i = 0; i < 16; i++) {
#pragma unroll
            for (int k = 0; k < 3; k++) {
                float a2 = at[i][0] * z[0 * 3 + k] + at[i][1] * z[1 * 3 + k] + at[i][2] * z[2 * 3 + k];
                sA2[((o0 + i) * 3 + k) * 32 + s] = a2;
            }
        }
    }

    // ---- v-pass: v = WvT^T @ g ; vp = v + pr stays in REGISTERS ----
    float vp[16][3];
    {
        unsigned long long vpp[8][3];
#pragma unroll
        for (int jp = 0; jp < 8; jp++)
#pragma unroll
            for (int d = 0; d < 3; d++) vpp[jp][d] = 0ull;
#pragma unroll 2
        for (int c = 0; c < 64; c++) {
            unsigned long long g0p = pack2(sG[c * 96 + s]);
            unsigned long long g1p = pack2(sG[c * 96 + 32 + s]);
            unsigned long long g2p = pack2(sG[c * 96 + 64 + s]);
            const ulonglong2* w2 = (const ulonglong2*)(sWb + c * 128 + o0);
            ulonglong2 wa = w2[0], wb = w2[1], wc = w2[2], wd = w2[3];
            ffma2(vpp[0][0], wa.x, g0p); ffma2(vpp[0][1], wa.x, g1p); ffma2(vpp[0][2], wa.x, g2p);
            ffma2(vpp[1][0], wa.y, g0p); ffma2(vpp[1][1], wa.y, g1p); ffma2(vpp[1][2], wa.y, g2p);
            ffma2(vpp[2][0], wb.x, g0p); ffma2(vpp[2][1], wb.x, g1p); ffma2(vpp[2][2], wb.x, g2p);
            ffma2(vpp[3][0], wb.y, g0p); ffma2(vpp[3][1], wb.y, g1p); ffma2(vpp[3][2], wb.y, g2p);
            ffma2(vpp[4][0], wc.x, g0p); ffma2(vpp[4][1], wc.x, g1p); ffma2(vpp[4][2], wc.x, g2p);
            ffma2(vpp[5][0], wc.y, g0p); ffma2(vpp[5][1], wc.y, g1p); ffma2(vpp[5][2], wc.y, g2p);
            ffma2(vpp[6][0], wd.x, g0p); ffma2(vpp[6][1], wd.x, g1p); ffma2(vpp[6][2], wd.x, g2p);
            ffma2(vpp[7][0], wd.y, g0p); ffma2(vpp[7][1], wd.y, g1p); ffma2(vpp[7][2], wd.y, g2p);
        }
#pragma unroll
        for (int jp = 0; jp < 8; jp++) {
            int ia = jp * 2, ib = jp * 2 + 1;
            float wra = sWr[o0 + ia], wrb = sWr[o0 + ib];
            float2 v0 = unpack2(vpp[jp][0]);
            float2 v1 = unpack2(vpp[jp][1]);
            float2 v2 = unpack2(vpp[jp][2]);
            vp[ia][0] = v0.x + wra * xr0;  vp[ib][0] = v0.y + wrb * xr0;
            vp[ia][1] = v1.x + wra * xr1;  vp[ib][1] = v1.y + wrb * xr1;
            vp[ia][2] = v2.x + wra * xr2;  vp[ib][2] = v2.y + wrb * xr2;
        }
    }
    __syncthreads();   // sA2 complete; sG/sWb dead -> sH/sAx aliases safe

    // ---- f1 GEMM (o-pair layout): thread = (o-pair pr, s-quarter sq) ----
    const int pr = tid & 63, sq = tid >> 6;
    {
        unsigned long long f0[4], f1[4];
#pragma unroll
        for (int q = 0; q < 4; q++) { f0[q] = 0ull; f1[q] = 0ull; }
        float2 wcur = __ldg((const float2*)(d_Wf1T) + pr);
#pragma unroll 4
        for (int c = 0; c < 384; c++) {
            float2 wnxt = __ldg((const float2*)(d_Wf1T + (c + 1) * 128) + pr);
            unsigned long long w0p = pack2(wcur.x);
            unsigned long long w1p = pack2(wcur.y);
            const ulonglong2* av = (const ulonglong2*)(sA2 + c * 32 + sq * 8);
            ulonglong2 a01 = av[0], a23 = av[1];
            ffma2(f0[0], a01.x, w0p); ffma2(f0[1], a01.y, w0p);
            ffma2(f0[2], a23.x, w0p); ffma2(f0[3], a23.y, w0p);
            ffma2(f1[0], a01.x, w1p); ffma2(f1[1], a01.y, w1p);
            ffma2(f1[2], a23.x, w1p); ffma2(f1[3], a23.y, w1p);
            wcur = wnxt;
        }
        float2 bb = __ldg((const float2*)bf1 + pr);
        float2* h0 = (float2*)(sH + (2 * pr) * 36 + sq * 8);
        float2* h1 = (float2*)(sH + (2 * pr + 1) * 36 + sq * 8);
#pragma unroll
        for (int q = 0; q < 4; q++) {
            float2 a = unpack2(f0[q]);
            float2 c = unpack2(f1[q]);
            h0[q] = make_float2(fmaxf(a.x + bb.x, 0.f), fmaxf(a.y + bb.x, 0.f));
            h1[q] = make_float2(fmaxf(c.x + bb.y, 0.f), fmaxf(c.y + bb.y, 0.f));
        }
    }
    __syncthreads();

    // ---- f2 GEMM (o-pair layout); logits -> sAx ----
    {
        unsigned long long f0[4], f1[4];
#pragma unroll
        for (int q = 0; q < 4; q++) { f0[q] = 0ull; f1[q] = 0ull; }
        float2 wcur = __ldg((const float2*)(d_Wf2T) + pr);
#pragma unroll 4
        for (int c = 0; c < 128; c++) {
            float2 wnxt = __ldg((const float2*)(d_Wf2T + (c + 1) * 128) + pr);
            unsigned long long w0p = pack2(wcur.x);
            unsigned long long w1p = pack2(wcur.y);
            const ulonglong2* hv = (const ulonglong2*)(sH + c * 36 + sq * 8);
            ulonglong2 h01 = hv[0], h23 = hv[1];
            ffma2(f0[0], h01.x, w0p); ffma2(f0[1], h01.y, w0p);
            ffma2(f0[2], h23.x, w0p); ffma2(f0[3], h23.y, w0p);
            ffma2(f1[0], h01.x, w1p); ffma2(f1[1], h01.y, w1p);
            ffma2(f1[2], h23.x, w1p); ffma2(f1[3], h23.y, w1p);
            wcur = wnxt;
        }
        float2 bb = __ldg((const float2*)d_bf2s + pr);
        float2* x0 = (float2*)(sAx + (2 * pr) * 34 + sq * 8);
        float2* x1 = (float2*)(sAx + (2 * pr + 1) * 34 + sq * 8);
#pragma unroll
        for (int q = 0; q < 4; q++) {
            float2 a = unpack2(f0[q]);
            float2 c = unpack2(f1[q]);
            x0[q] = make_float2(a.x + bb.x, a.y + bb.x);
            x1[q] = make_float2(c.x + bb.y, c.y + bb.y);
        }
    }
    __syncthreads();

    // ---- softmax over s + weighted sum over s (vp already in regs) ----
#pragma unroll 2
    for (int i = 0; i < 16; i++) {
        int o = o0 + i;
        float x = sAx[o * 34 + s];
        float m = wmax(x);
        float e = __expf(x - m);
        float denom = wsum(e);
        float w = e / denom;
        float r0 = wsum(w * vp[i][0]);
        float r1 = wsum(w * vp[i][1]);
        float r2 = wsum(w * vp[i][2]);
        if (s == 0) {
            size_t base = (((size_t)b * 128 + o) * 3) * 1024 + n;
            out[base] = r0;
            out[base + 1024] = r1;
            out[base + 2048] = r2;
        }
    }
}

extern "C" void kernel_launch(void* const* d_in, const int* in_sizes, int n_in,
                              void* d_out, int out_size) {
    (void)in_sizes; (void)n_in; (void)out_size;
    const float* gxyz = (const float*)d_in[0];
    const float* gfts = (const float*)d_in[1];
    const float* qxyz = (const float*)d_in[2];
    cudaFuncSetAttribute(main_kernel, cudaFuncAttributeMaxDynamicSharedMemorySize, SMEM_BYTES);
    prep1_kernel<<<128, 64>>>((const float*)d_in[3], (const float*)d_in[4]);
    prep2_kernel<<<128, 64>>>((const float*)d_in[5],  (const float*)d_in[6],
                              (const float*)d_in[7],  (const float*)d_in[8],
                              (const float*)d_in[9],  (const float*)d_in[11],
                              (const float*)d_in[13], (const float*)d_in[14]);
    q_kernel<<<NPTS, 128>>>(gfts);
    main_kernel<<<NPTS, 256, SMEM_BYTES>>>(gxyz, gfts, qxyz,
                                           (const float*)d_in[10],
                                           (const float*)d_in[12],
                                           (float*)d_out);
}